// round 3
// baseline (speedup 1.0000x reference)
#include <cuda_runtime.h>
#include <math.h>

#define NB 32
#define NL 128
#define NH 512
#define NG 2048
#define NV 32000
#define NE 128
#define NTOK 4096
#define NVT 250

// ------------------ scratch ------------------
__device__ float g_x0[NTOK * NE];
__device__ float g_gx[2u * NTOK * NG];          // [dir][m][g], m = b*128+t
__device__ float g_bufA[NTOK * 1024];
__device__ float g_bufB[NTOK * 1024];
__device__ float g_hid[NTOK * 128];
__device__ float g_h[2 * NB * NH];
__device__ float g_c[2 * NB * NH];
__device__ float g_part[2 * 4 * NG * NB];       // [dir][ks][g][b]
__device__ float g_pmax[(size_t)NTOK * NVT];
__device__ float g_psum[(size_t)NTOK * NVT];
__device__ int   g_parg[(size_t)NTOK * NVT];
__device__ float g_nllw[NTOK];
__device__ float g_wtok[NTOK];
__device__ unsigned int g_barcnt;

// ------------------ helpers ------------------
__device__ __forceinline__ float sigf(float x) {
    return 1.0f / (1.0f + __expf(-x));
}
__device__ __forceinline__ float tanhf_fast(float x) {
    float e = __expf(-2.0f * fabsf(x));
    float r = (1.0f - e) / (1.0f + e);
    return copysignf(r, x);
}

__device__ __forceinline__ void gridbar() {
    __syncthreads();
    if (threadIdx.x == 0) {
        __threadfence();
        unsigned int t = atomicAdd(&g_barcnt, 1u);
        unsigned int need = ((t >> 7) + 1u) << 7;   // /128, +1, *128
        while (*((volatile unsigned int*)&g_barcnt) < need) {
            __nanosleep(32);
        }
    }
    __syncthreads();
}

// ------------------ embedding ------------------
__global__ __launch_bounds__(256) void k_embed(const int* __restrict__ w,
                                               const float* __restrict__ emb) {
    int i = blockIdx.x * 256 + threadIdx.x;      // 0 .. NTOK*NE-1
    g_x0[i] = emb[(size_t)w[i >> 7] * NE + (i & 127)];
}

// ------------------ zero h/c + barrier ------------------
__global__ __launch_bounds__(256) void k_zero() {
    int i = blockIdx.x * 256 + threadIdx.x;
    if (i < 2 * NB * NH) { g_h[i] = 0.0f; g_c[i] = 0.0f; }
    if (i == 0) g_barcnt = 0u;
}

// ------------------ generic SGEMM: C[m][n] = act(sum_k A[m][k]*W[n][k] + bias[n]) ------------------
// 64x64 tile, BK=16, 256 threads, 4x4 microtile. blockIdx.z = dir.
__global__ __launch_bounds__(256) void k_gemm(const float* __restrict__ A,
                                              const float* __restrict__ W,
                                              const float* __restrict__ bias,
                                              float* __restrict__ C,
                                              int K, int N,
                                              long long wStr, long long bStr,
                                              long long cStr, int relu) {
    int d = blockIdx.z;
    W += (size_t)d * wStr;
    bias += (size_t)d * bStr;
    C += (size_t)d * cStr;

    __shared__ float As[16 * 68];
    __shared__ float Bs[16 * 68];

    int tid = threadIdx.x;
    int m0 = blockIdx.y << 6, n0 = blockIdx.x << 6;
    int lr = tid >> 2, lk = (tid & 3) << 2;
    int tm = tid >> 4, tn = tid & 15;

    const float* Ap = A + (size_t)(m0 + lr) * K + lk;
    const float* Wp = W + (size_t)(n0 + lr) * K + lk;

    float acc[4][4];
#pragma unroll
    for (int i = 0; i < 4; i++)
#pragma unroll
        for (int j = 0; j < 4; j++) acc[i][j] = 0.0f;

    for (int k0 = 0; k0 < K; k0 += 16) {
        float4 av = *(const float4*)(Ap + k0);
        float4 wv = *(const float4*)(Wp + k0);
        As[(lk + 0) * 68 + lr] = av.x; As[(lk + 1) * 68 + lr] = av.y;
        As[(lk + 2) * 68 + lr] = av.z; As[(lk + 3) * 68 + lr] = av.w;
        Bs[(lk + 0) * 68 + lr] = wv.x; Bs[(lk + 1) * 68 + lr] = wv.y;
        Bs[(lk + 2) * 68 + lr] = wv.z; Bs[(lk + 3) * 68 + lr] = wv.w;
        __syncthreads();
#pragma unroll
        for (int k = 0; k < 16; k++) {
            float4 a = *(const float4*)&As[k * 68 + (tm << 2)];
            float4 b = *(const float4*)&Bs[k * 68 + (tn << 2)];
            acc[0][0] += a.x * b.x; acc[0][1] += a.x * b.y; acc[0][2] += a.x * b.z; acc[0][3] += a.x * b.w;
            acc[1][0] += a.y * b.x; acc[1][1] += a.y * b.y; acc[1][2] += a.y * b.z; acc[1][3] += a.y * b.w;
            acc[2][0] += a.z * b.x; acc[2][1] += a.z * b.y; acc[2][2] += a.z * b.z; acc[2][3] += a.z * b.w;
            acc[3][0] += a.w * b.x; acc[3][1] += a.w * b.y; acc[3][2] += a.w * b.z; acc[3][3] += a.w * b.w;
        }
        __syncthreads();
    }
#pragma unroll
    for (int i = 0; i < 4; i++) {
        int m = m0 + (tm << 2) + i;
#pragma unroll
        for (int j = 0; j < 4; j++) {
            int n = n0 + (tn << 2) + j;
            float v = acc[i][j] + bias[n];
            if (relu) v = fmaxf(v, 0.0f);
            C[(size_t)m * N + n] = v;
        }
    }
}

// ------------------ persistent BiLSTM layer scan ------------------
// 128 blocks x 128 threads. gemm role: (dir, ksplit, gate-tile). combine role: (dir, j-tile).
__global__ __launch_bounds__(128) void k_scan(const float* __restrict__ gx,
                                              const float* __restrict__ whh,
                                              const float* __restrict__ mask,
                                              float* __restrict__ out) {
    __shared__ float Hs[32 * 129];
    __shared__ float Ws[128 * 17];

    int tid = threadIdx.x;
    int bid = blockIdx.x;
    int d = bid >> 6;
    int ks = (bid >> 4) & 3;
    int gt = bid & 15;
    int g0 = gt << 7;
    int k0 = ks << 7;
    const float* whhd = whh + (size_t)d * NG * NH;

    int tg = tid >> 3;   // 0..15 (8 gate rows each)
    int tb = tid & 7;    // 0..7  (4 batches each)

    int jt = bid & 63;   // combine: 8 j per tile
    int jl = tid & 7;
    int bq = tid >> 3;   // 0..15

    for (int s = 0; s < NL; s++) {
        // ---- recurrent GEMM partial ----
        {
            int hb = tid >> 2;
            int hk = (tid & 3) << 5;
            const float* hp = g_h + (size_t)(d * NB + hb) * NH + k0 + hk;
            float* dst = &Hs[hb * 129 + hk];
#pragma unroll
            for (int q = 0; q < 8; q++) {
                float4 v = __ldcg((const float4*)(hp + q * 4));
                dst[q * 4 + 0] = v.x; dst[q * 4 + 1] = v.y;
                dst[q * 4 + 2] = v.z; dst[q * 4 + 3] = v.w;
            }
        }
        float acc[8][4];
#pragma unroll
        for (int i = 0; i < 8; i++)
#pragma unroll
            for (int j = 0; j < 4; j++) acc[i][j] = 0.0f;

        const float* wrow = whhd + (size_t)(g0 + tid) * NH + k0;
        for (int kc = 0; kc < 8; kc++) {
            __syncthreads();
            {
                float4 w0 = *(const float4*)(wrow + kc * 16 + 0);
                float4 w1 = *(const float4*)(wrow + kc * 16 + 4);
                float4 w2 = *(const float4*)(wrow + kc * 16 + 8);
                float4 w3 = *(const float4*)(wrow + kc * 16 + 12);
                float* wd = &Ws[tid * 17];
                wd[0] = w0.x;  wd[1] = w0.y;  wd[2] = w0.z;  wd[3] = w0.w;
                wd[4] = w1.x;  wd[5] = w1.y;  wd[6] = w1.z;  wd[7] = w1.w;
                wd[8] = w2.x;  wd[9] = w2.y;  wd[10] = w2.z; wd[11] = w2.w;
                wd[12] = w3.x; wd[13] = w3.y; wd[14] = w3.z; wd[15] = w3.w;
            }
            __syncthreads();
#pragma unroll
            for (int k = 0; k < 16; k++) {
                float hv[4];
#pragma unroll
                for (int j = 0; j < 4; j++)
                    hv[j] = Hs[(tb * 4 + j) * 129 + (kc << 4) + k];
#pragma unroll
                for (int i = 0; i < 8; i++) {
                    float w = Ws[((tg << 3) + i) * 17 + k];
#pragma unroll
                    for (int j = 0; j < 4; j++) acc[i][j] += w * hv[j];
                }
            }
        }
        // write partials
        {
            size_t pbase = ((size_t)(d * 4 + ks) * NG + g0) * NB;
#pragma unroll
            for (int i = 0; i < 8; i++)
#pragma unroll
                for (int j = 0; j < 4; j++)
                    g_part[pbase + (size_t)((tg << 3) + i) * NB + tb * 4 + j] = acc[i][j];
        }
        __threadfence();
        gridbar();

        // ---- combine: gates -> cell update ----
        int t = d ? (NL - 1 - s) : s;
#pragma unroll
        for (int rep = 0; rep < 2; rep++) {
            int b = bq + (rep << 4);
            int j = (jt << 3) + jl;
            float gate[4];
#pragma unroll
            for (int gi = 0; gi < 4; gi++) {
                int g = gi * NH + j;
                float v = gx[((size_t)d * NTOK + (size_t)b * NL + t) * NG + g];
#pragma unroll
                for (int kss = 0; kss < 4; kss++)
                    v += __ldcg(&g_part[((size_t)(d * 4 + kss) * NG + g) * NB + b]);
                gate[gi] = v;
            }
            float ivg = sigf(gate[0]);
            float fvg = sigf(gate[1]);
            float gvg = tanhf_fast(gate[2]);
            float ovg = sigf(gate[3]);
            size_t hidx = (size_t)(d * NB + b) * NH + j;
            float cold = __ldcg(&g_c[hidx]);
            float cnew = fvg * cold + ivg * gvg;
            float hnew = ovg * tanhf_fast(cnew);
            float mt = mask[b * NL + t];
            float hold = __ldcg(&g_h[hidx]);
            float hh = hold + (hnew - hold) * mt;
            float cc = cold + (cnew - cold) * mt;
            g_c[hidx] = cc;
            g_h[hidx] = hh;
            out[((size_t)b * NL + t) * 1024 + d * NH + j] = hh;
        }
        __threadfence();
        gridbar();
    }
}

// ------------------ decoder2: logits tile + online softmax partials ------------------
// block = (vtile 128 v, mtile 64 tokens); 256 threads; 4m x 8n microtile; K=128.
__global__ __launch_bounds__(256) void k_dec2(const float* __restrict__ w2,
                                              const float* __restrict__ b2) {
    int vt = blockIdx.x;   // 0..249
    int mt = blockIdx.y;   // 0..63
    int v0 = vt << 7, m0 = mt << 6;

    __shared__ float Ash[32 * 68];
    __shared__ float Wsh[32 * 132];
    __shared__ float rmax[1024];
    __shared__ int   rarg[1024];
    __shared__ float smax[64];

    int tid = threadIdx.x;
    int tm = tid >> 4, tn = tid & 15;

    float acc[4][8];
#pragma unroll
    for (int i = 0; i < 4; i++)
#pragma unroll
        for (int j = 0; j < 8; j++) acc[i][j] = 0.0f;

    for (int kc = 0; kc < 4; kc++) {
        int kb = kc << 5;
        __syncthreads();
        {
            int ar = tid >> 2, akq = (tid & 3) << 3;
            const float* ap = g_hid + (size_t)(m0 + ar) * 128 + kb + akq;
            float4 u0 = *(const float4*)ap;
            float4 u1 = *(const float4*)(ap + 4);
            Ash[(akq + 0) * 68 + ar] = u0.x; Ash[(akq + 1) * 68 + ar] = u0.y;
            Ash[(akq + 2) * 68 + ar] = u0.z; Ash[(akq + 3) * 68 + ar] = u0.w;
            Ash[(akq + 4) * 68 + ar] = u1.x; Ash[(akq + 5) * 68 + ar] = u1.y;
            Ash[(akq + 6) * 68 + ar] = u1.z; Ash[(akq + 7) * 68 + ar] = u1.w;

            int wr = tid >> 1, wkq = (tid & 1) << 4;
            const float* wp = w2 + (size_t)(v0 + wr) * 128 + kb + wkq;
            float4 q0 = *(const float4*)wp;
            float4 q1 = *(const float4*)(wp + 4);
            float4 q2 = *(const float4*)(wp + 8);
            float4 q3 = *(const float4*)(wp + 12);
            Wsh[(wkq + 0) * 132 + wr] = q0.x;  Wsh[(wkq + 1) * 132 + wr] = q0.y;
            Wsh[(wkq + 2) * 132 + wr] = q0.z;  Wsh[(wkq + 3) * 132 + wr] = q0.w;
            Wsh[(wkq + 4) * 132 + wr] = q1.x;  Wsh[(wkq + 5) * 132 + wr] = q1.y;
            Wsh[(wkq + 6) * 132 + wr] = q1.z;  Wsh[(wkq + 7) * 132 + wr] = q1.w;
            Wsh[(wkq + 8) * 132 + wr] = q2.x;  Wsh[(wkq + 9) * 132 + wr] = q2.y;
            Wsh[(wkq + 10) * 132 + wr] = q2.z; Wsh[(wkq + 11) * 132 + wr] = q2.w;
            Wsh[(wkq + 12) * 132 + wr] = q3.x; Wsh[(wkq + 13) * 132 + wr] = q3.y;
            Wsh[(wkq + 14) * 132 + wr] = q3.z; Wsh[(wkq + 15) * 132 + wr] = q3.w;
        }
        __syncthreads();
#pragma unroll
        for (int k = 0; k < 32; k++) {
            float4 a = *(const float4*)&Ash[k * 68 + (tm << 2)];
            float4 w0 = *(const float4*)&Wsh[k * 132 + (tn << 3)];
            float4 w1 = *(const float4*)&Wsh[k * 132 + (tn << 3) + 4];
            float av[4] = {a.x, a.y, a.z, a.w};
            float wv[8] = {w0.x, w0.y, w0.z, w0.w, w1.x, w1.y, w1.z, w1.w};
#pragma unroll
            for (int i = 0; i < 4; i++)
#pragma unroll
                for (int j = 0; j < 8; j++) acc[i][j] += av[i] * wv[j];
        }
    }

    // add bias, per-thread per-m local max/arg
#pragma unroll
    for (int i = 0; i < 4; i++) {
        int ml = tm * 4 + i;
        float lm = -1e30f;
        int la = 0;
#pragma unroll
        for (int j = 0; j < 8; j++) {
            int v = v0 + (tn << 3) + j;
            float lg = acc[i][j] + b2[v];
            acc[i][j] = lg;
            if (lg > lm) { lm = lg; la = v; }
        }
        rmax[ml * 16 + tn] = lm;
        rarg[ml * 16 + tn] = la;
    }
    __syncthreads();
    if (tid < 64) {
        float bm = -1e30f;
        int ba = 0;
        for (int q = 0; q < 16; q++) {
            float v = rmax[tid * 16 + q];
            if (v > bm) { bm = v; ba = rarg[tid * 16 + q]; }
        }
        smax[tid] = bm;
        g_pmax[(size_t)(m0 + tid) * NVT + vt] = bm;
        g_parg[(size_t)(m0 + tid) * NVT + vt] = ba;
    }
    __syncthreads();
#pragma unroll
    for (int i = 0; i < 4; i++) {
        int ml = tm * 4 + i;
        float s = 0.0f;
        float mx = smax[ml];
#pragma unroll
        for (int j = 0; j < 8; j++) s += __expf(acc[i][j] - mx);
        rmax[ml * 16 + tn] = s;   // reuse as sum buffer
    }
    __syncthreads();
    if (tid < 64) {
        float s = 0.0f;
        for (int q = 0; q < 16; q++) s += rmax[tid * 16 + q];
        g_psum[(size_t)(m0 + tid) * NVT + vt] = s;
    }
}

// ------------------ per-token combine: lse, argmax, weighted nll ------------------
__global__ __launch_bounds__(256) void k_comb(const float* __restrict__ w2,
                                              const float* __restrict__ b2,
                                              const int* __restrict__ tgt,
                                              const float* __restrict__ cew,
                                              float* __restrict__ dout) {
    int warp = threadIdx.x >> 5, lane = threadIdx.x & 31;
    int m = blockIdx.x * 8 + warp;

    float lm = -1e30f, ls = 0.0f;
    int la = 0;
    for (int vt = lane; vt < NVT; vt += 32) {
        float tmx = g_pmax[(size_t)m * NVT + vt];
        float tsm = g_psum[(size_t)m * NVT + vt];
        int tag = g_parg[(size_t)m * NVT + vt];
        if (tmx > lm) {
            ls = ls * __expf(lm - tmx) + tsm;
            lm = tmx;
            la = tag;
        } else {
            ls += tsm * __expf(tmx - lm);
        }
    }
#pragma unroll
    for (int off = 16; off; off >>= 1) {
        float om = __shfl_down_sync(0xffffffffu, lm, off);
        float os = __shfl_down_sync(0xffffffffu, ls, off);
        int oa = __shfl_down_sync(0xffffffffu, la, off);
        float nm = fmaxf(lm, om);
        float ns = ls * __expf(lm - nm) + os * __expf(om - nm);
        int na = (om > lm) ? oa : ((om == lm && oa < la) ? oa : la);
        lm = nm; ls = ns; la = na;
    }

    // target logit: 128-dot per token, warp-parallel
    int tg = tgt[m];
    float4 hv = *(const float4*)&g_hid[(size_t)m * 128 + lane * 4];
    float4 wv = *(const float4*)&w2[(size_t)tg * 128 + lane * 4];
    float dp = hv.x * wv.x + hv.y * wv.y + hv.z * wv.z + hv.w * wv.w;
#pragma unroll
    for (int off = 16; off; off >>= 1) dp += __shfl_down_sync(0xffffffffu, dp, off);

    if (lane == 0) {
        float logit_t = dp + b2[tg];
        float lse = lm + logf(ls);
        float nll = lse - logit_t;
        float w = cew[tg];
        g_nllw[m] = nll * w;
        g_wtok[m] = w;
        dout[1 + m] = (float)la;
    }
}

// ------------------ final loss reduce ------------------
__global__ __launch_bounds__(256) void k_loss(float* __restrict__ dout) {
    __shared__ float s1[256];
    __shared__ float s2[256];
    int tid = threadIdx.x;
    float a = 0.0f, b = 0.0f;
    for (int i = tid; i < NTOK; i += 256) { a += g_nllw[i]; b += g_wtok[i]; }
    s1[tid] = a; s2[tid] = b;
    __syncthreads();
    for (int off = 128; off; off >>= 1) {
        if (tid < off) { s1[tid] += s1[tid + off]; s2[tid] += s2[tid + off]; }
        __syncthreads();
    }
    if (tid == 0) dout[0] = s1[0] / s2[0];
}

// ------------------ launch ------------------
extern "C" void kernel_launch(void* const* d_in, const int* in_sizes, int n_in,
                              void* d_out, int out_size) {
    const int* inp_word = (const int*)d_in[0];
    const float* inp_mask = (const float*)d_in[1];
    // d_in[2] = pri_mask (unused by reference)
    const int* tgt_word = (const int*)d_in[3];
    const float* emb = (const float*)d_in[4];
    const float* w_ih0 = (const float*)d_in[5];
    const float* w_hh0 = (const float*)d_in[6];
    const float* b0 = (const float*)d_in[7];
    const float* w_ih = (const float*)d_in[8];
    const float* w_hh = (const float*)d_in[9];
    const float* bb = (const float*)d_in[10];
    const float* dec_w1 = (const float*)d_in[11];
    const float* dec_b1 = (const float*)d_in[12];
    const float* dec_w2 = (const float*)d_in[13];
    const float* dec_b2 = (const float*)d_in[14];
    const float* cew = (const float*)d_in[15];
    float* out = (float*)d_out;

    float *px0, *pgx, *pA, *pB, *phid;
    cudaGetSymbolAddress((void**)&px0, g_x0);
    cudaGetSymbolAddress((void**)&pgx, g_gx);
    cudaGetSymbolAddress((void**)&pA, g_bufA);
    cudaGetSymbolAddress((void**)&pB, g_bufB);
    cudaGetSymbolAddress((void**)&phid, g_hid);

    // 1. embedding
    k_embed<<<(NTOK * NE) / 256, 256>>>(inp_word, emb);

    // 2. layer 0: gx = x @ Wih0^T + b0 (both dirs)
    k_gemm<<<dim3(NG / 64, NTOK / 64, 2), 256>>>(px0, w_ih0, b0, pgx,
                                                 NE, NG,
                                                 (long long)NG * NE, NG,
                                                 (long long)NTOK * NG, 0);
    k_zero<<<128, 256>>>();
    k_scan<<<128, 128>>>(pgx, w_hh0, inp_mask, pA);

    // 3. layer 1
    k_gemm<<<dim3(NG / 64, NTOK / 64, 2), 256>>>(pA, w_ih, bb, pgx,
                                                 1024, NG,
                                                 (long long)NG * 1024, NG,
                                                 (long long)NTOK * NG, 0);
    k_zero<<<128, 256>>>();
    k_scan<<<128, 128>>>(pgx, w_hh, inp_mask, pB);

    // 4. layer 2
    k_gemm<<<dim3(NG / 64, NTOK / 64, 2), 256>>>(pB, w_ih + (size_t)2 * NG * 1024,
                                                 bb + 2 * NG, pgx,
                                                 1024, NG,
                                                 (long long)NG * 1024, NG,
                                                 (long long)NTOK * NG, 0);
    k_zero<<<128, 256>>>();
    k_scan<<<128, 128>>>(pgx, w_hh + (size_t)2 * NG * NH, inp_mask, pA);

    // 5. decoder layer 1 (relu)
    k_gemm<<<dim3(128 / 64, NTOK / 64, 1), 256>>>(pA, dec_w1, dec_b1, phid,
                                                  1024, 128, 0, 0, 0, 1);

    // 6. decoder layer 2 + fused online softmax partials
    k_dec2<<<dim3(NVT, NTOK / 64), 256>>>(dec_w2, dec_b2);

    // 7. per-token combine
    k_comb<<<NTOK / 8, 256>>>(dec_w2, dec_b2, tgt_word, cew, out);

    // 8. loss reduce
    k_loss<<<1, 256>>>(out);
}